// round 6
// baseline (speedup 1.0000x reference)
#include <cuda_runtime.h>
#include <cuda_bf16.h>
#include <math.h>
#include <stdint.h>

#define NB 4
#define NH 16
#define NT 2048
#define NE 1024
#define ND 64
#define NM (NB*NT)   // 8192

// ---------------- scratch (__device__ globals; alloc-free rule) -------------
__device__ __nv_bfloat16 g_qhi[NB*NH*NT*ND];
__device__ __nv_bfloat16 g_qlo[NB*NH*NT*ND];
__device__ __nv_bfloat16 g_khi[NB*NH*NT*ND];
__device__ __nv_bfloat16 g_klo[NB*NH*NT*ND];
__device__ __nv_bfloat16 g_vhi[NB*NH*NT*ND];
__device__ __nv_bfloat16 g_vlo[NB*NH*NT*ND];
__device__ __nv_bfloat16 g_xhi[NM*NE];
__device__ __nv_bfloat16 g_xlo[NM*NE];
__device__ __nv_bfloat16 g_whi[NE*NE];
__device__ __nv_bfloat16 g_wlo[NE*NE];

// ---------------- helpers ----------------------------------------------------
__device__ __forceinline__ uint32_t smem_u32(const void* p) {
    uint32_t a;
    asm("{ .reg .u64 t; cvta.to.shared.u64 t, %1; cvt.u32.u64 %0, t; }" : "=r"(a) : "l"(p));
    return a;
}
__device__ __forceinline__ void ldsm_x4(uint32_t& r0, uint32_t& r1, uint32_t& r2,
                                        uint32_t& r3, uint32_t addr) {
    asm volatile("ldmatrix.sync.aligned.m8n8.x4.shared.b16 {%0,%1,%2,%3}, [%4];"
                 : "=r"(r0), "=r"(r1), "=r"(r2), "=r"(r3) : "r"(addr));
}
__device__ __forceinline__ void ldsm_x4_t(uint32_t& r0, uint32_t& r1, uint32_t& r2,
                                          uint32_t& r3, uint32_t addr) {
    asm volatile("ldmatrix.sync.aligned.m8n8.x4.trans.shared.b16 {%0,%1,%2,%3}, [%4];"
                 : "=r"(r0), "=r"(r1), "=r"(r2), "=r"(r3) : "r"(addr));
}
__device__ __forceinline__ void mma_bf16(float* c, const uint32_t* a,
                                         uint32_t b0, uint32_t b1) {
    asm volatile(
        "mma.sync.aligned.m16n8k16.row.col.f32.bf16.bf16.f32 "
        "{%0,%1,%2,%3}, {%4,%5,%6,%7}, {%8,%9}, {%0,%1,%2,%3};"
        : "+f"(c[0]), "+f"(c[1]), "+f"(c[2]), "+f"(c[3])
        : "r"(a[0]), "r"(a[1]), "r"(a[2]), "r"(a[3]), "r"(b0), "r"(b1));
}
__device__ __forceinline__ uint32_t pack_bf16(float x, float y) {
    __nv_bfloat162 t = __floats2bfloat162_rn(x, y);
    return *reinterpret_cast<uint32_t*>(&t);
}
__device__ __forceinline__ void split2(float x, float y, uint32_t& h, uint32_t& l) {
    __nv_bfloat162 hh = __floats2bfloat162_rn(x, y);
    h = *reinterpret_cast<uint32_t*>(&hh);
    l = pack_bf16(x - __low2float(hh), y - __high2float(hh));
}
#define CP_ASYNC16(dst, src) \
    asm volatile("cp.async.cg.shared.global [%0], [%1], 16;" :: "r"(dst), "l"(src))
#define CP_COMMIT() asm volatile("cp.async.commit_group;" ::: "memory")
#define CP_WAIT(n)  asm volatile("cp.async.wait_group %0;" :: "n"(n) : "memory")

// ---------------------------------------------------------------------------
// fp32 -> (bf16 hi, bf16 lo) split conversion
// ---------------------------------------------------------------------------
__global__ __launch_bounds__(256) void conv_split(const float4* __restrict__ in,
                                                  uint2* __restrict__ hi,
                                                  uint2* __restrict__ lo, int n4) {
    int i = blockIdx.x * 256 + threadIdx.x;
    if (i >= n4) return;
    float4 v = in[i];
    uint32_t h01, l01, h23, l23;
    split2(v.x, v.y, h01, l01);
    split2(v.z, v.w, h23, l23);
    hi[i] = make_uint2(h01, h23);
    lo[i] = make_uint2(l01, l23);
}

// ---------------------------------------------------------------------------
// HMMA bf16x3 GEMM: C = X @ W^T + bias (optionally *scale).
// Pass-major mma ordering: 16 independent accumulators between reuses.
// MODE 0: fp32 out C[m*NE+n].  MODE 1: bf16 hi/lo scatter to [B,H,T,D].
// ---------------------------------------------------------------------------
#define PITCH_B 80
#define MAT_BYTES (128*PITCH_B)
#define STAGE_BYTES (4*MAT_BYTES)
#define NCHUNK (NE/32)

template<int MODE>
__global__ __launch_bounds__(256) void gemm_mma(
    const __nv_bfloat16* __restrict__ xhi, const __nv_bfloat16* __restrict__ xlo,
    const __nv_bfloat16* __restrict__ whi, const __nv_bfloat16* __restrict__ wlo,
    const float* __restrict__ bias, float* __restrict__ C,
    __nv_bfloat16* __restrict__ Chi, __nv_bfloat16* __restrict__ Clo, float scale)
{
    extern __shared__ __align__(256) char smem[];
    const uint32_t sb = smem_u32(smem);
    const int tid = threadIdx.x;
    const int wid = tid >> 5, lane = tid & 31;
    const int wm = wid >> 1, wn = wid & 1;
    const int n0 = blockIdx.x * 128, m0 = blockIdx.y * 128;

    const __nv_bfloat16* bases[4] = { xhi, xlo, whi, wlo };

    const int lr = lane & 15;
    const int kb8 = (lane >> 4) << 4;
    uint32_t aoff[2], boff[4];
    #pragma unroll
    for (int i = 0; i < 2; ++i)
        aoff[i] = (uint32_t)((wm*32 + i*16 + lr) * PITCH_B + kb8);
    #pragma unroll
    for (int j = 0; j < 4; ++j)
        boff[j] = (uint32_t)((wn*64 + j*16 + lr) * PITCH_B + kb8);

    float acc[2][8][4];
    #pragma unroll
    for (int i = 0; i < 2; ++i)
        #pragma unroll
        for (int j = 0; j < 8; ++j)
            #pragma unroll
            for (int r = 0; r < 4; ++r) acc[i][j][r] = 0.f;

    auto load_stage = [&](int stage, int kt) {
        const uint32_t sbase = sb + stage * STAGE_BYTES;
        #pragma unroll
        for (int t = 0; t < 4; ++t) {
            #pragma unroll
            for (int it = 0; it < 2; ++it) {
                int idx = tid + it * 256;
                int row = idx >> 2, c16 = idx & 3;
                int rg = ((t < 2) ? m0 : n0) + row;
                const __nv_bfloat16* src = bases[t] + (long)rg * NE + kt + c16 * 8;
                uint32_t dst = sbase + t * MAT_BYTES + row * PITCH_B + c16 * 16;
                CP_ASYNC16(dst, src);
            }
        }
        CP_COMMIT();
    };

    load_stage(0, 0);

    for (int c = 0; c < NCHUNK; ++c) {
        if (c + 1 < NCHUNK) {
            load_stage((c + 1) & 1, (c + 1) * 32);
            CP_WAIT(1);
        } else {
            CP_WAIT(0);
        }
        __syncthreads();

        const uint32_t sA_hi = sb + (c & 1) * STAGE_BYTES;
        const uint32_t sA_lo = sA_hi + MAT_BYTES;
        const uint32_t sB_hi = sA_hi + 2 * MAT_BYTES;
        const uint32_t sB_lo = sA_hi + 3 * MAT_BYTES;

        #pragma unroll
        for (int ks = 0; ks < 2; ++ks) {
            const uint32_t kbyte = ks * 32;
            uint32_t ah[2][4], al[2][4], bh[4][4], bl[4][4];
            #pragma unroll
            for (int i = 0; i < 2; ++i) {
                ldsm_x4(ah[i][0], ah[i][1], ah[i][2], ah[i][3], sA_hi + aoff[i] + kbyte);
                ldsm_x4(al[i][0], al[i][1], al[i][2], al[i][3], sA_lo + aoff[i] + kbyte);
            }
            #pragma unroll
            for (int j = 0; j < 4; ++j) {
                ldsm_x4(bh[j][0], bh[j][1], bh[j][2], bh[j][3], sB_hi + boff[j] + kbyte);
                ldsm_x4(bl[j][0], bl[j][1], bl[j][2], bl[j][3], sB_lo + boff[j] + kbyte);
            }
            // pass 1: hi*hi  (16 independent accumulators)
            #pragma unroll
            for (int i = 0; i < 2; ++i)
                #pragma unroll
                for (int j = 0; j < 4; ++j) {
                    mma_bf16(acc[i][2*j],   ah[i], bh[j][0], bh[j][2]);
                    mma_bf16(acc[i][2*j+1], ah[i], bh[j][1], bh[j][3]);
                }
            // pass 2: hi*lo
            #pragma unroll
            for (int i = 0; i < 2; ++i)
                #pragma unroll
                for (int j = 0; j < 4; ++j) {
                    mma_bf16(acc[i][2*j],   ah[i], bl[j][0], bl[j][2]);
                    mma_bf16(acc[i][2*j+1], ah[i], bl[j][1], bl[j][3]);
                }
            // pass 3: lo*hi
            #pragma unroll
            for (int i = 0; i < 2; ++i)
                #pragma unroll
                for (int j = 0; j < 4; ++j) {
                    mma_bf16(acc[i][2*j],   al[i], bh[j][0], bh[j][2]);
                    mma_bf16(acc[i][2*j+1], al[i], bh[j][1], bh[j][3]);
                }
        }
        __syncthreads();
    }

    const int qr = lane >> 2, qc = (lane & 3) * 2;
    #pragma unroll
    for (int i = 0; i < 2; ++i) {
        #pragma unroll
        for (int j = 0; j < 8; ++j) {
            const int n = n0 + wn*64 + j*8 + qc;
            const float b0 = bias[n], b1 = bias[n + 1];
            #pragma unroll
            for (int r8 = 0; r8 < 2; ++r8) {
                const int m = m0 + wm*32 + i*16 + qr + r8*8;
                float vx = acc[i][j][r8*2]     + b0;
                float vy = acc[i][j][r8*2 + 1] + b1;
                if (MODE == 0) {
                    *reinterpret_cast<float2*>(&C[(long)m * NE + n]) = make_float2(vx, vy);
                } else {
                    vx *= scale; vy *= scale;
                    uint32_t hp, lp;
                    split2(vx, vy, hp, lp);
                    const int b = m >> 11, t = m & 2047, h = n >> 6, d = n & 63;
                    const long off = ((((long)(b*NH + h) * NT) + t) << 6) + d;
                    *reinterpret_cast<uint32_t*>(&Chi[off]) = hp;
                    *reinterpret_cast<uint32_t*>(&Clo[off]) = lp;
                }
            }
        }
    }
}

// ---------------------------------------------------------------------------
// Tensor-core causal flash attention (bf16x3), pass-major mma ordering.
// ---------------------------------------------------------------------------
#define APITCH 144
#define QBYTES (128*APITCH)
#define KVMAT  (64*APITCH)
#define KVSTAGE (4*KVMAT)
#define OFF_KV (2*QBYTES)
#define ATTN_SMEM (OFF_KV + 2*KVSTAGE)   // 110592

__global__ __launch_bounds__(256) void attn_mma()
{
    extern __shared__ __align__(256) char smem[];
    const uint32_t sb = smem_u32(smem);
    const int tid = threadIdx.x, wid = tid >> 5, lane = tid & 31;
    const int qt = blockIdx.x;
    const int h = blockIdx.y, b = blockIdx.z;

    const long hb = (long)(b*NH + h) * NT * ND;
    const __nv_bfloat16* srcsQ[2] = { g_qhi + hb + (long)qt*128*ND, g_qlo + hb + (long)qt*128*ND };
    const __nv_bfloat16* srcsKV[4] = { g_khi + hb, g_klo + hb, g_vhi + hb, g_vlo + hb };

    #pragma unroll
    for (int t = 0; t < 2; ++t) {
        #pragma unroll
        for (int it = 0; it < 4; ++it) {
            int idx = tid + it * 256;
            int row = idx >> 3, c16 = idx & 7;
            CP_ASYNC16(sb + t*QBYTES + row*APITCH + c16*16,
                       srcsQ[t] + (long)row*ND + c16*8);
        }
    }
    auto load_kv = [&](int stage, int kt) {
        const uint32_t sbase = sb + OFF_KV + stage * KVSTAGE;
        #pragma unroll
        for (int t = 0; t < 4; ++t) {
            #pragma unroll
            for (int it = 0; it < 2; ++it) {
                int idx = tid + it * 256;
                int row = idx >> 3, c16 = idx & 7;
                CP_ASYNC16(sbase + t*KVMAT + row*APITCH + c16*16,
                           srcsKV[t] + (long)(kt*64 + row)*ND + c16*8);
            }
        }
        CP_COMMIT();
    };
    load_kv(0, 0);

    const int lr = lane & 15;
    const int kb16 = (lane >> 4) << 4;
    const uint32_t aoffQ = (uint32_t)((wid*16 + lr) * APITCH + kb16);
    const uint32_t koff  = (uint32_t)(lr * APITCH + kb16);

    float m0 = -INFINITY, m1 = -INFINITY, l0 = 0.f, l1 = 0.f;
    float o[8][4];
    #pragma unroll
    for (int j = 0; j < 8; ++j)
        #pragma unroll
        for (int r = 0; r < 4; ++r) o[j][r] = 0.f;

    const int nkt = 2*qt + 2;
    const int rowg0 = qt*128 + wid*16 + (lane >> 2);
    const int qc2 = (lane & 3) * 2;

    for (int kt = 0; kt < nkt; ++kt) {
        if (kt + 1 < nkt) { load_kv((kt + 1) & 1, kt + 1); CP_WAIT(1); }
        else              { CP_WAIT(0); }
        __syncthreads();

        const uint32_t sK_hi = sb + OFF_KV + (kt & 1) * KVSTAGE;
        const uint32_t sK_lo = sK_hi + KVMAT;
        const uint32_t sV_hi = sK_hi + 2*KVMAT;
        const uint32_t sV_lo = sK_hi + 3*KVMAT;

        // ---- S = Q @ K^T (bf16x3, pass-major) ----
        float s[8][4];
        #pragma unroll
        for (int j = 0; j < 8; ++j)
            #pragma unroll
            for (int r = 0; r < 4; ++r) s[j][r] = 0.f;

        #pragma unroll
        for (int ks = 0; ks < 4; ++ks) {
            const uint32_t kb = ks * 32;
            uint32_t ah[4], al[4], bh[4][4], bl[4][4];
            ldsm_x4(ah[0], ah[1], ah[2], ah[3], sb + aoffQ + kb);
            ldsm_x4(al[0], al[1], al[2], al[3], sb + QBYTES + aoffQ + kb);
            #pragma unroll
            for (int t = 0; t < 4; ++t) {
                ldsm_x4(bh[t][0], bh[t][1], bh[t][2], bh[t][3], sK_hi + koff + t*16*APITCH + kb);
                ldsm_x4(bl[t][0], bl[t][1], bl[t][2], bl[t][3], sK_lo + koff + t*16*APITCH + kb);
            }
            #pragma unroll
            for (int t = 0; t < 4; ++t) {
                mma_bf16(s[2*t],   ah, bh[t][0], bh[t][2]);
                mma_bf16(s[2*t+1], ah, bh[t][1], bh[t][3]);
            }
            #pragma unroll
            for (int t = 0; t < 4; ++t) {
                mma_bf16(s[2*t],   ah, bl[t][0], bl[t][2]);
                mma_bf16(s[2*t+1], ah, bl[t][1], bl[t][3]);
            }
            #pragma unroll
            for (int t = 0; t < 4; ++t) {
                mma_bf16(s[2*t],   al, bh[t][0], bh[t][2]);
                mma_bf16(s[2*t+1], al, bh[t][1], bh[t][3]);
            }
        }

        // ---- causal mask (only diagonal-straddling tiles) ----
        if (kt >= 2*qt) {
            const int colbase = kt*64 + qc2;
            #pragma unroll
            for (int j = 0; j < 8; ++j) {
                int c0 = colbase + j*8, c1 = c0 + 1;
                if (c0 > rowg0)     s[j][0] = -1e30f;
                if (c1 > rowg0)     s[j][1] = -1e30f;
                if (c0 > rowg0 + 8) s[j][2] = -1e30f;
                if (c1 > rowg0 + 8) s[j][3] = -1e30f;
            }
        }

        // ---- streaming softmax ----
        float rm0 = -1e30f, rm1 = -1e30f;
        #pragma unroll
        for (int j = 0; j < 8; ++j) {
            rm0 = fmaxf(rm0, fmaxf(s[j][0], s[j][1]));
            rm1 = fmaxf(rm1, fmaxf(s[j][2], s[j][3]));
        }
        rm0 = fmaxf(rm0, __shfl_xor_sync(0xffffffffu, rm0, 1));
        rm0 = fmaxf(rm0, __shfl_xor_sync(0xffffffffu, rm0, 2));
        rm1 = fmaxf(rm1, __shfl_xor_sync(0xffffffffu, rm1, 1));
        rm1 = fmaxf(rm1, __shfl_xor_sync(0xffffffffu, rm1, 2));
        const float mn0 = fmaxf(m0, rm0), mn1 = fmaxf(m1, rm1);
        const float cr0 = __expf(m0 - mn0), cr1 = __expf(m1 - mn1);
        float sum0 = 0.f, sum1 = 0.f;
        #pragma unroll
        for (int j = 0; j < 8; ++j) {
            s[j][0] = __expf(s[j][0] - mn0);
            s[j][1] = __expf(s[j][1] - mn0);
            s[j][2] = __expf(s[j][2] - mn1);
            s[j][3] = __expf(s[j][3] - mn1);
            sum0 += s[j][0] + s[j][1];
            sum1 += s[j][2] + s[j][3];
        }
        sum0 += __shfl_xor_sync(0xffffffffu, sum0, 1);
        sum0 += __shfl_xor_sync(0xffffffffu, sum0, 2);
        sum1 += __shfl_xor_sync(0xffffffffu, sum1, 1);
        sum1 += __shfl_xor_sync(0xffffffffu, sum1, 2);
        l0 = l0*cr0 + sum0; l1 = l1*cr1 + sum1;
        m0 = mn0; m1 = mn1;
        #pragma unroll
        for (int j = 0; j < 8; ++j) {
            o[j][0] *= cr0; o[j][1] *= cr0;
            o[j][2] *= cr1; o[j][3] *= cr1;
        }

        // ---- O += P @ V (bf16x3, pass-major, V via ldmatrix.trans) ----
        #pragma unroll
        for (int ks = 0; ks < 4; ++ks) {
            uint32_t ph[4], pl[4];
            {
                const float* r0 = s[2*ks];
                const float* r1 = s[2*ks+1];
                split2(r0[0], r0[1], ph[0], pl[0]);
                split2(r0[2], r0[3], ph[1], pl[1]);
                split2(r1[0], r1[1], ph[2], pl[2]);
                split2(r1[2], r1[3], ph[3], pl[3]);
            }
            const uint32_t vrow = (uint32_t)((ks*16 + lr) * APITCH + kb16);
            uint32_t vh[4][4], vl[4][4];
            #pragma unroll
            for (int t = 0; t < 4; ++t) {
                ldsm_x4_t(vh[t][0], vh[t][1], vh[t][2], vh[t][3], sV_hi + vrow + t*32);
                ldsm_x4_t(vl[t][0], vl[t][1], vl[t][2], vl[t][3], sV_lo + vrow + t*32);
            }
            #pragma unroll
            for (int t = 0; t < 4; ++t) {
                mma_bf16(o[2*t],   ph, vh[t][0], vh[t][1]);
                mma_bf16(o[2*t+1], ph, vh[t][2], vh[t][3]);
            }
            #pragma unroll
            for (int t = 0; t < 4; ++t) {
                mma_bf16(o[2*t],   ph, vl[t][0], vl[t][1]);
                mma_bf16(o[2*t+1], ph, vl[t][2], vl[t][3]);
            }
            #pragma unroll
            for (int t = 0; t < 4; ++t) {
                mma_bf16(o[2*t],   pl, vh[t][0], vh[t][1]);
                mma_bf16(o[2*t+1], pl, vh[t][2], vh[t][3]);
            }
        }
        __syncthreads();
    }

    // ---- finalize: O /= l, write pre-split into O-projection inputs ----
    const float il0 = 1.f / l0, il1 = 1.f / l1;
    const int t0 = qt*128 + wid*16 + (lane >> 2);
    const long rowbase = ((long)b*NT + t0) * NE + h*64;
    #pragma unroll
    for (int j = 0; j < 8; ++j) {
        const int d = j*8 + qc2;
        uint32_t hp, lp;
        split2(o[j][0]*il0, o[j][1]*il0, hp, lp);
        *reinterpret_cast<uint32_t*>(&g_xhi[rowbase + d]) = hp;
        *reinterpret_cast<uint32_t*>(&g_xlo[rowbase + d]) = lp;
        split2(o[j][2]*il1, o[j][3]*il1, hp, lp);
        *reinterpret_cast<uint32_t*>(&g_xhi[rowbase + 8*NE + d]) = hp;
        *reinterpret_cast<uint32_t*>(&g_xlo[rowbase + 8*NE + d]) = lp;
    }
}

// ---------------------------------------------------------------------------
extern "C" void kernel_launch(void* const* d_in, const int* in_sizes, int n_in,
                              void* d_out, int out_size)
{
    const float* query  = (const float*)d_in[0];
    const float* key_in = (const float*)d_in[1];
    const float* value  = (const float*)d_in[2];
    // d_in[3] = mask (exact tril -> causal predicate, not read)
    const float* Wq = (const float*)d_in[4];
    const float* bq = (const float*)d_in[5];
    const float* Wk = (const float*)d_in[6];
    const float* bk = (const float*)d_in[7];
    const float* Wv = (const float*)d_in[8];
    const float* bv = (const float*)d_in[9];
    const float* Wo = (const float*)d_in[10];
    const float* bo = (const float*)d_in[11];
    float* out = (float*)d_out;

    __nv_bfloat16 *qhi, *qlo, *khi, *klo, *vhi, *vlo, *xhi, *xlo, *whi, *wlo;
    cudaGetSymbolAddress((void**)&qhi, g_qhi);
    cudaGetSymbolAddress((void**)&qlo, g_qlo);
    cudaGetSymbolAddress((void**)&khi, g_khi);
    cudaGetSymbolAddress((void**)&klo, g_klo);
    cudaGetSymbolAddress((void**)&vhi, g_vhi);
    cudaGetSymbolAddress((void**)&vlo, g_vlo);
    cudaGetSymbolAddress((void**)&xhi, g_xhi);
    cudaGetSymbolAddress((void**)&xlo, g_xlo);
    cudaGetSymbolAddress((void**)&whi, g_whi);
    cudaGetSymbolAddress((void**)&wlo, g_wlo);

    const int gemm_smem = 2 * STAGE_BYTES;   // 81920
    cudaFuncSetAttribute(gemm_mma<0>, cudaFuncAttributeMaxDynamicSharedMemorySize, gemm_smem);
    cudaFuncSetAttribute(gemm_mma<1>, cudaFuncAttributeMaxDynamicSharedMemorySize, gemm_smem);
    cudaFuncSetAttribute(attn_mma, cudaFuncAttributeMaxDynamicSharedMemorySize, ATTN_SMEM);

    const int n4x = NM * NE / 4;
    const int n4w = NE * NE / 4;
    dim3 gridG(NE / 128, NM / 128);
    const float qscale = 0.125f;   // 1/sqrt(D)

    conv_split<<<n4x / 256, 256>>>((const float4*)query, (uint2*)xhi, (uint2*)xlo, n4x);
    conv_split<<<n4w / 256, 256>>>((const float4*)Wq, (uint2*)whi, (uint2*)wlo, n4w);
    gemm_mma<1><<<gridG, 256, gemm_smem>>>(xhi, xlo, whi, wlo, bq, nullptr, qhi, qlo, qscale);

    conv_split<<<n4x / 256, 256>>>((const float4*)key_in, (uint2*)xhi, (uint2*)xlo, n4x);
    conv_split<<<n4w / 256, 256>>>((const float4*)Wk, (uint2*)whi, (uint2*)wlo, n4w);
    gemm_mma<1><<<gridG, 256, gemm_smem>>>(xhi, xlo, whi, wlo, bk, nullptr, khi, klo, 1.f);

    conv_split<<<n4x / 256, 256>>>((const float4*)value, (uint2*)xhi, (uint2*)xlo, n4x);
    conv_split<<<n4w / 256, 256>>>((const float4*)Wv, (uint2*)whi, (uint2*)wlo, n4w);
    gemm_mma<1><<<gridG, 256, gemm_smem>>>(xhi, xlo, whi, wlo, bv, nullptr, vhi, vlo, 1.f);

    attn_mma<<<dim3(16, NH, NB), 256, ATTN_SMEM>>>();   // writes xhi/xlo

    conv_split<<<n4w / 256, 256>>>((const float4*)Wo, (uint2*)whi, (uint2*)wlo, n4w);
    gemm_mma<0><<<gridG, 256, gemm_smem>>>(xhi, xlo, whi, wlo, bo, out, nullptr, nullptr, 1.f);
}

// round 7
// speedup vs baseline: 2.2748x; 2.2748x over previous
#include <cuda_runtime.h>
#include <cuda_fp16.h>
#include <math.h>
#include <stdint.h>

#define NB 4
#define NH 16
#define NT 2048
#define NE 1024
#define ND 64
#define NM (NB*NT)   // 8192

// ---------------- scratch (__device__ globals; alloc-free rule) -------------
__device__ __half g_qh[NB*NH*NT*ND];
__device__ __half g_kh[NB*NH*NT*ND];
__device__ __half g_vh[NB*NH*NT*ND];
__device__ __half g_xh[NM*NE];
__device__ __half g_wh[NE*NE];

// ---------------- helpers ----------------------------------------------------
__device__ __forceinline__ uint32_t smem_u32(const void* p) {
    uint32_t a;
    asm("{ .reg .u64 t; cvta.to.shared.u64 t, %1; cvt.u32.u64 %0, t; }" : "=r"(a) : "l"(p));
    return a;
}
__device__ __forceinline__ void ldsm_x4(uint32_t& r0, uint32_t& r1, uint32_t& r2,
                                        uint32_t& r3, uint32_t addr) {
    asm volatile("ldmatrix.sync.aligned.m8n8.x4.shared.b16 {%0,%1,%2,%3}, [%4];"
                 : "=r"(r0), "=r"(r1), "=r"(r2), "=r"(r3) : "r"(addr));
}
__device__ __forceinline__ void ldsm_x4_t(uint32_t& r0, uint32_t& r1, uint32_t& r2,
                                          uint32_t& r3, uint32_t addr) {
    asm volatile("ldmatrix.sync.aligned.m8n8.x4.trans.shared.b16 {%0,%1,%2,%3}, [%4];"
                 : "=r"(r0), "=r"(r1), "=r"(r2), "=r"(r3) : "r"(addr));
}
__device__ __forceinline__ void mma_f16(float* c, const uint32_t* a,
                                        uint32_t b0, uint32_t b1) {
    asm volatile(
        "mma.sync.aligned.m16n8k16.row.col.f32.f16.f16.f32 "
        "{%0,%1,%2,%3}, {%4,%5,%6,%7}, {%8,%9}, {%0,%1,%2,%3};"
        : "+f"(c[0]), "+f"(c[1]), "+f"(c[2]), "+f"(c[3])
        : "r"(a[0]), "r"(a[1]), "r"(a[2]), "r"(a[3]), "r"(b0), "r"(b1));
}
__device__ __forceinline__ uint32_t pack_h2(float x, float y) {
    __half2 t = __floats2half2_rn(x, y);
    return *reinterpret_cast<uint32_t*>(&t);
}
#define CP_ASYNC16(dst, src) \
    asm volatile("cp.async.cg.shared.global [%0], [%1], 16;" :: "r"(dst), "l"(src))
#define CP_COMMIT() asm volatile("cp.async.commit_group;" ::: "memory")
#define CP_WAIT(n)  asm volatile("cp.async.wait_group %0;" :: "n"(n) : "memory")

// ---------------------------------------------------------------------------
// fp32 -> fp16 conversion, vectorized
// ---------------------------------------------------------------------------
__global__ __launch_bounds__(256) void conv_half(const float4* __restrict__ in,
                                                 uint2* __restrict__ out, int n4) {
    int i = blockIdx.x * 256 + threadIdx.x;
    if (i >= n4) return;
    float4 v = in[i];
    out[i] = make_uint2(pack_h2(v.x, v.y), pack_h2(v.z, v.w));
}

// ---------------------------------------------------------------------------
// fp16 HMMA GEMM: C = X @ W^T + bias (optionally *scale).
// Block 128x128, 8 warps (4Mx2N), warp tile 32x64, K-chunk 32,
// cp.async double-buffered.  MODE 0: fp32 out.  MODE 1: fp16 scatter [B,H,T,D].
// ---------------------------------------------------------------------------
#define PITCH_B 80                 // 32 fp16 = 64B + 16B pad
#define MAT_BYTES (128*PITCH_B)    // 10240
#define STAGE_BYTES (2*MAT_BYTES)  // A, B = 20480
#define NCHUNK (NE/32)

template<int MODE>
__global__ __launch_bounds__(256) void gemm_f16(
    const __half* __restrict__ X, const __half* __restrict__ W,
    const float* __restrict__ bias, float* __restrict__ C,
    __half* __restrict__ Ch, float scale)
{
    extern __shared__ __align__(256) char smem[];
    const uint32_t sb = smem_u32(smem);
    const int tid = threadIdx.x;
    const int wid = tid >> 5, lane = tid & 31;
    const int wm = wid >> 1, wn = wid & 1;
    const int n0 = blockIdx.x * 128, m0 = blockIdx.y * 128;

    const __half* bases[2] = { X, W };

    const int lr = lane & 15;
    const int kb8 = (lane >> 4) << 4;
    uint32_t aoff[2], boff[4];
    #pragma unroll
    for (int i = 0; i < 2; ++i)
        aoff[i] = (uint32_t)((wm*32 + i*16 + lr) * PITCH_B + kb8);
    #pragma unroll
    for (int j = 0; j < 4; ++j)
        boff[j] = (uint32_t)((wn*64 + j*16 + lr) * PITCH_B + kb8);

    float acc[2][8][4];
    #pragma unroll
    for (int i = 0; i < 2; ++i)
        #pragma unroll
        for (int j = 0; j < 8; ++j)
            #pragma unroll
            for (int r = 0; r < 4; ++r) acc[i][j][r] = 0.f;

    auto load_stage = [&](int stage, int kt) {
        const uint32_t sbase = sb + stage * STAGE_BYTES;
        #pragma unroll
        for (int t = 0; t < 2; ++t) {
            #pragma unroll
            for (int it = 0; it < 2; ++it) {
                int idx = tid + it * 256;          // 512 = 128 rows x 4x16B
                int row = idx >> 2, c16 = idx & 3;
                int rg = ((t == 0) ? m0 : n0) + row;
                const __half* src = bases[t] + (long)rg * NE + kt + c16 * 8;
                uint32_t dst = sbase + t * MAT_BYTES + row * PITCH_B + c16 * 16;
                CP_ASYNC16(dst, src);
            }
        }
        CP_COMMIT();
    };

    load_stage(0, 0);

    for (int c = 0; c < NCHUNK; ++c) {
        if (c + 1 < NCHUNK) {
            load_stage((c + 1) & 1, (c + 1) * 32);
            CP_WAIT(1);
        } else {
            CP_WAIT(0);
        }
        __syncthreads();

        const uint32_t sA = sb + (c & 1) * STAGE_BYTES;
        const uint32_t sB = sA + MAT_BYTES;

        #pragma unroll
        for (int ks = 0; ks < 2; ++ks) {
            const uint32_t kbyte = ks * 32;
            uint32_t a[2][4], bmat[4][4];
            #pragma unroll
            for (int i = 0; i < 2; ++i)
                ldsm_x4(a[i][0], a[i][1], a[i][2], a[i][3], sA + aoff[i] + kbyte);
            #pragma unroll
            for (int j = 0; j < 4; ++j)
                ldsm_x4(bmat[j][0], bmat[j][1], bmat[j][2], bmat[j][3], sB + boff[j] + kbyte);
            #pragma unroll
            for (int i = 0; i < 2; ++i)
                #pragma unroll
                for (int j = 0; j < 4; ++j) {
                    mma_f16(acc[i][2*j],   a[i], bmat[j][0], bmat[j][2]);
                    mma_f16(acc[i][2*j+1], a[i], bmat[j][1], bmat[j][3]);
                }
        }
        __syncthreads();
    }

    const int qr = lane >> 2, qc = (lane & 3) * 2;
    #pragma unroll
    for (int i = 0; i < 2; ++i) {
        #pragma unroll
        for (int j = 0; j < 8; ++j) {
            const int n = n0 + wn*64 + j*8 + qc;
            const float b0 = bias[n], b1 = bias[n + 1];
            #pragma unroll
            for (int r8 = 0; r8 < 2; ++r8) {
                const int m = m0 + wm*32 + i*16 + qr + r8*8;
                float vx = acc[i][j][r8*2]     + b0;
                float vy = acc[i][j][r8*2 + 1] + b1;
                if (MODE == 0) {
                    *reinterpret_cast<float2*>(&C[(long)m * NE + n]) = make_float2(vx, vy);
                } else {
                    const int b = m >> 11, t = m & 2047, h = n >> 6, d = n & 63;
                    const long off = ((((long)(b*NH + h) * NT) + t) << 6) + d;
                    *reinterpret_cast<uint32_t*>(&Ch[off]) = pack_h2(vx * scale, vy * scale);
                }
            }
        }
    }
}

// ---------------------------------------------------------------------------
// fp16 tensor-core causal flash attention.
// CTA: 128 q-rows x (head, batch); 8 warps, each 16 q-rows x 64 kv-cols.
// Q/K/V already fp16 in gmem (1/sqrt(D) folded into Q by its projection).
// cp.async double-buffered KV; V via ldmatrix.trans; output fp16 -> g_xh.
// ---------------------------------------------------------------------------
#define APITCH 144                 // 64 fp16 = 128B + 16B pad
#define QBYTES (128*APITCH)        // 18432
#define KVMAT  (64*APITCH)         // 9216
#define KVSTAGE (2*KVMAT)          // K, V = 18432
#define OFF_KV QBYTES
#define ATTN_SMEM (OFF_KV + 2*KVSTAGE)   // 55296

__global__ __launch_bounds__(256) void attn_f16()
{
    extern __shared__ __align__(256) char smem[];
    const uint32_t sb = smem_u32(smem);
    const int tid = threadIdx.x, wid = tid >> 5, lane = tid & 31;
    const int qt = blockIdx.x;
    const int h = blockIdx.y, b = blockIdx.z;

    const long hb = (long)(b*NH + h) * NT * ND;
    const __half* Qg = g_qh + hb + (long)qt*128*ND;
    const __half* srcsKV[2] = { g_kh + hb, g_vh + hb };

    // Q load: 1024 x 16B, 4 per thread
    #pragma unroll
    for (int it = 0; it < 4; ++it) {
        int idx = tid + it * 256;
        int row = idx >> 3, c16 = idx & 7;
        CP_ASYNC16(sb + row*APITCH + c16*16, Qg + (long)row*ND + c16*8);
    }
    auto load_kv = [&](int stage, int kt) {
        const uint32_t sbase = sb + OFF_KV + stage * KVSTAGE;
        #pragma unroll
        for (int t = 0; t < 2; ++t) {
            #pragma unroll
            for (int it = 0; it < 2; ++it) {
                int idx = tid + it * 256;          // 512 = 64 rows x 8
                int row = idx >> 3, c16 = idx & 7;
                CP_ASYNC16(sbase + t*KVMAT + row*APITCH + c16*16,
                           srcsKV[t] + (long)(kt*64 + row)*ND + c16*8);
            }
        }
        CP_COMMIT();
    };
    load_kv(0, 0);   // commits Q + stage0

    const int lr = lane & 15;
    const int kb16 = (lane >> 4) << 4;
    const uint32_t aoffQ = (uint32_t)((wid*16 + lr) * APITCH + kb16);
    const uint32_t koff  = (uint32_t)(lr * APITCH + kb16);

    float m0 = -INFINITY, m1 = -INFINITY, l0 = 0.f, l1 = 0.f;
    float o[8][4];
    #pragma unroll
    for (int j = 0; j < 8; ++j)
        #pragma unroll
        for (int r = 0; r < 4; ++r) o[j][r] = 0.f;

    const int nkt = 2*qt + 2;
    const int rowg0 = qt*128 + wid*16 + (lane >> 2);
    const int qc2 = (lane & 3) * 2;

    for (int kt = 0; kt < nkt; ++kt) {
        if (kt + 1 < nkt) { load_kv((kt + 1) & 1, kt + 1); CP_WAIT(1); }
        else              { CP_WAIT(0); }
        __syncthreads();

        const uint32_t sK = sb + OFF_KV + (kt & 1) * KVSTAGE;
        const uint32_t sV = sK + KVMAT;

        // ---- S = Q @ K^T ----
        float s[8][4];
        #pragma unroll
        for (int j = 0; j < 8; ++j)
            #pragma unroll
            for (int r = 0; r < 4; ++r) s[j][r] = 0.f;

        #pragma unroll
        for (int ks = 0; ks < 4; ++ks) {
            const uint32_t kb = ks * 32;
            uint32_t a[4], bm[4][4];
            ldsm_x4(a[0], a[1], a[2], a[3], sb + aoffQ + kb);
            #pragma unroll
            for (int t = 0; t < 4; ++t)
                ldsm_x4(bm[t][0], bm[t][1], bm[t][2], bm[t][3], sK + koff + t*16*APITCH + kb);
            #pragma unroll
            for (int t = 0; t < 4; ++t) {
                mma_f16(s[2*t],   a, bm[t][0], bm[t][2]);
                mma_f16(s[2*t+1], a, bm[t][1], bm[t][3]);
            }
        }

        // ---- causal mask (diagonal-straddling tiles only) ----
        if (kt >= 2*qt) {
            const int colbase = kt*64 + qc2;
            #pragma unroll
            for (int j = 0; j < 8; ++j) {
                int c0 = colbase + j*8, c1 = c0 + 1;
                if (c0 > rowg0)     s[j][0] = -1e30f;
                if (c1 > rowg0)     s[j][1] = -1e30f;
                if (c0 > rowg0 + 8) s[j][2] = -1e30f;
                if (c1 > rowg0 + 8) s[j][3] = -1e30f;
            }
        }

        // ---- streaming softmax ----
        float rm0 = -1e30f, rm1 = -1e30f;
        #pragma unroll
        for (int j = 0; j < 8; ++j) {
            rm0 = fmaxf(rm0, fmaxf(s[j][0], s[j][1]));
            rm1 = fmaxf(rm1, fmaxf(s[j][2], s[j][3]));
        }
        rm0 = fmaxf(rm0, __shfl_xor_sync(0xffffffffu, rm0, 1));
        rm0 = fmaxf(rm0, __shfl_xor_sync(0xffffffffu, rm0, 2));
        rm1 = fmaxf(rm1, __shfl_xor_sync(0xffffffffu, rm1, 1));
        rm1 = fmaxf(rm1, __shfl_xor_sync(0xffffffffu, rm1, 2));
        const float mn0 = fmaxf(m0, rm0), mn1 = fmaxf(m1, rm1);
        const float cr0 = __expf(m0 - mn0), cr1 = __expf(m1 - mn1);
        float sum0 = 0.f, sum1 = 0.f;
        #pragma unroll
        for (int j = 0; j < 8; ++j) {
            s[j][0] = __expf(s[j][0] - mn0);
            s[j][1] = __expf(s[j][1] - mn0);
            s[j][2] = __expf(s[j][2] - mn1);
            s[j][3] = __expf(s[j][3] - mn1);
            sum0 += s[j][0] + s[j][1];
            sum1 += s[j][2] + s[j][3];
        }
        sum0 += __shfl_xor_sync(0xffffffffu, sum0, 1);
        sum0 += __shfl_xor_sync(0xffffffffu, sum0, 2);
        sum1 += __shfl_xor_sync(0xffffffffu, sum1, 1);
        sum1 += __shfl_xor_sync(0xffffffffu, sum1, 2);
        l0 = l0*cr0 + sum0; l1 = l1*cr1 + sum1;
        m0 = mn0; m1 = mn1;
        #pragma unroll
        for (int j = 0; j < 8; ++j) {
            o[j][0] *= cr0; o[j][1] *= cr0;
            o[j][2] *= cr1; o[j][3] *= cr1;
        }

        // ---- O += P @ V (V via ldmatrix.trans) ----
        #pragma unroll
        for (int ks = 0; ks < 4; ++ks) {
            uint32_t p[4];
            {
                const float* r0 = s[2*ks];
                const float* r1 = s[2*ks+1];
                p[0] = pack_h2(r0[0], r0[1]);
                p[1] = pack_h2(r0[2], r0[3]);
                p[2] = pack_h2(r1[0], r1[1]);
                p[3] = pack_h2(r1[2], r1[3]);
            }
            const uint32_t vrow = (uint32_t)((ks*16 + lr) * APITCH + kb16);
            uint32_t v[4][4];
            #pragma unroll
            for (int t = 0; t < 4; ++t)
                ldsm_x4_t(v[t][0], v[t][1], v[t][2], v[t][3], sV + vrow + t*32);
            #pragma unroll
            for (int t = 0; t < 4; ++t) {
                mma_f16(o[2*t],   p, v[t][0], v[t][1]);
                mma_f16(o[2*t+1], p, v[t][2], v[t][3]);
            }
        }
        __syncthreads();   // release kv stage
    }

    // ---- finalize: O /= l, write fp16 into O-projection input ----
    const float il0 = 1.f / l0, il1 = 1.f / l1;
    const int t0 = qt*128 + wid*16 + (lane >> 2);
    const long rowbase = ((long)b*NT + t0) * NE + h*64;
    #pragma unroll
    for (int j = 0; j < 8; ++j) {
        const int d = j*8 + qc2;
        *reinterpret_cast<uint32_t*>(&g_xh[rowbase + d]) =
            pack_h2(o[j][0]*il0, o[j][1]*il0);
        *reinterpret_cast<uint32_t*>(&g_xh[rowbase + 8*NE + d]) =
            pack_h2(o[j][2]*il1, o[j][3]*il1);
    }
}

// ---------------------------------------------------------------------------
extern "C" void kernel_launch(void* const* d_in, const int* in_sizes, int n_in,
                              void* d_out, int out_size)
{
    const float* query  = (const float*)d_in[0];
    const float* key_in = (const float*)d_in[1];
    const float* value  = (const float*)d_in[2];
    // d_in[3] = mask (exact tril -> causal predicate, not read)
    const float* Wq = (const float*)d_in[4];
    const float* bq = (const float*)d_in[5];
    const float* Wk = (const float*)d_in[6];
    const float* bk = (const float*)d_in[7];
    const float* Wv = (const float*)d_in[8];
    const float* bv = (const float*)d_in[9];
    const float* Wo = (const float*)d_in[10];
    const float* bo = (const float*)d_in[11];
    float* out = (float*)d_out;

    __half *qh, *kh, *vh, *xh, *wh;
    cudaGetSymbolAddress((void**)&qh, g_qh);
    cudaGetSymbolAddress((void**)&kh, g_kh);
    cudaGetSymbolAddress((void**)&vh, g_vh);
    cudaGetSymbolAddress((void**)&xh, g_xh);
    cudaGetSymbolAddress((void**)&wh, g_wh);

    const int gemm_smem = 2 * STAGE_BYTES;   // 40960
    cudaFuncSetAttribute(gemm_f16<0>, cudaFuncAttributeMaxDynamicSharedMemorySize, gemm_smem);
    cudaFuncSetAttribute(gemm_f16<1>, cudaFuncAttributeMaxDynamicSharedMemorySize, gemm_smem);
    cudaFuncSetAttribute(attn_f16, cudaFuncAttributeMaxDynamicSharedMemorySize, ATTN_SMEM);

    const int n4x = NM * NE / 4;
    const int n4w = NE * NE / 4;
    dim3 gridG(NE / 128, NM / 128);
    const float qscale = 0.125f;   // 1/sqrt(D)

    conv_half<<<n4x / 256, 256>>>((const float4*)query, (uint2*)xh, n4x);
    conv_half<<<n4w / 256, 256>>>((const float4*)Wq, (uint2*)wh, n4w);
    gemm_f16<1><<<gridG, 256, gemm_smem>>>(xh, wh, bq, nullptr, qh, qscale);

    conv_half<<<n4x / 256, 256>>>((const float4*)key_in, (uint2*)xh, n4x);
    conv_half<<<n4w / 256, 256>>>((const float4*)Wk, (uint2*)wh, n4w);
    gemm_f16<1><<<gridG, 256, gemm_smem>>>(xh, wh, bk, nullptr, kh, 1.f);

    conv_half<<<n4x / 256, 256>>>((const float4*)value, (uint2*)xh, n4x);
    conv_half<<<n4w / 256, 256>>>((const float4*)Wv, (uint2*)wh, n4w);
    gemm_f16<1><<<gridG, 256, gemm_smem>>>(xh, wh, bv, nullptr, vh, 1.f);

    attn_f16<<<dim3(16, NH, NB), 256, ATTN_SMEM>>>();   // writes xh

    conv_half<<<n4w / 256, 256>>>((const float4*)Wo, (uint2*)wh, n4w);
    gemm_f16<0><<<gridG, 256, gemm_smem>>>(xh, wh, bo, out, nullptr, 1.f);
}

// round 8
// speedup vs baseline: 2.6994x; 1.1866x over previous
#include <cuda_runtime.h>
#include <cuda_fp16.h>
#include <math.h>
#include <stdint.h>

#define NB 4
#define NH 16
#define NT 2048
#define NE 1024
#define ND 64
#define NM (NB*NT)   // 8192

// ---------------- scratch (__device__ globals; alloc-free rule) -------------
__device__ __half g_qh[NB*NH*NT*ND];
__device__ __half g_kh[NB*NH*NT*ND];
__device__ __half g_vh[NB*NH*NT*ND];
__device__ __half g_xq[NM*NE];
__device__ __half g_xk[NM*NE];
__device__ __half g_xv[NM*NE];
__device__ __half g_xo[NM*NE];     // attention output (O-proj input)
__device__ __half g_wq[NE*NE];
__device__ __half g_wk[NE*NE];
__device__ __half g_wv[NE*NE];
__device__ __half g_wo[NE*NE];

// ---------------- helpers ----------------------------------------------------
__device__ __forceinline__ uint32_t smem_u32(const void* p) {
    uint32_t a;
    asm("{ .reg .u64 t; cvta.to.shared.u64 t, %1; cvt.u32.u64 %0, t; }" : "=r"(a) : "l"(p));
    return a;
}
__device__ __forceinline__ void ldsm_x4(uint32_t& r0, uint32_t& r1, uint32_t& r2,
                                        uint32_t& r3, uint32_t addr) {
    asm volatile("ldmatrix.sync.aligned.m8n8.x4.shared.b16 {%0,%1,%2,%3}, [%4];"
                 : "=r"(r0), "=r"(r1), "=r"(r2), "=r"(r3) : "r"(addr));
}
__device__ __forceinline__ void ldsm_x4_t(uint32_t& r0, uint32_t& r1, uint32_t& r2,
                                          uint32_t& r3, uint32_t addr) {
    asm volatile("ldmatrix.sync.aligned.m8n8.x4.trans.shared.b16 {%0,%1,%2,%3}, [%4];"
                 : "=r"(r0), "=r"(r1), "=r"(r2), "=r"(r3) : "r"(addr));
}
__device__ __forceinline__ void mma_f16(float* c, const uint32_t* a,
                                        uint32_t b0, uint32_t b1) {
    asm volatile(
        "mma.sync.aligned.m16n8k16.row.col.f32.f16.f16.f32 "
        "{%0,%1,%2,%3}, {%4,%5,%6,%7}, {%8,%9}, {%0,%1,%2,%3};"
        : "+f"(c[0]), "+f"(c[1]), "+f"(c[2]), "+f"(c[3])
        : "r"(a[0]), "r"(a[1]), "r"(a[2]), "r"(a[3]), "r"(b0), "r"(b1));
}
__device__ __forceinline__ uint32_t pack_h2(float x, float y) {
    __half2 t = __floats2half2_rn(x, y);
    return *reinterpret_cast<uint32_t*>(&t);
}
__device__ __forceinline__ float ex2(float x) {
    float y;
    asm("ex2.approx.f32 %0, %1;" : "=f"(y) : "f"(x));
    return y;
}
#define CP_ASYNC16(dst, src) \
    asm volatile("cp.async.cg.shared.global [%0], [%1], 16;" :: "r"(dst), "l"(src))
#define CP_COMMIT() asm volatile("cp.async.commit_group;" ::: "memory")
#define CP_WAIT(n)  asm volatile("cp.async.wait_group %0;" :: "n"(n) : "memory")

// ---------------------------------------------------------------------------
// merged fp32 -> fp16 conversions (2 elems/thread for MLP)
// ---------------------------------------------------------------------------
__global__ __launch_bounds__(256) void conv_in3(
    const float4* __restrict__ a, const float4* __restrict__ b,
    const float4* __restrict__ c,
    uint2* __restrict__ oa, uint2* __restrict__ ob, uint2* __restrict__ oc)
{
    const int which = blockIdx.y;
    const float4* in = (which == 0) ? a : (which == 1) ? b : c;
    uint2* out = (which == 0) ? oa : (which == 1) ? ob : oc;
    const int n4 = NM * NE / 4;
    int i = blockIdx.x * 256 + threadIdx.x;
    float4 v0 = in[i], v1 = in[i + n4/2];
    out[i]        = make_uint2(pack_h2(v0.x, v0.y), pack_h2(v0.z, v0.w));
    out[i + n4/2] = make_uint2(pack_h2(v1.x, v1.y), pack_h2(v1.z, v1.w));
}
__global__ __launch_bounds__(256) void conv_w4(
    const float4* __restrict__ a, const float4* __restrict__ b,
    const float4* __restrict__ c, const float4* __restrict__ d,
    uint2* __restrict__ oa, uint2* __restrict__ ob,
    uint2* __restrict__ oc, uint2* __restrict__ od)
{
    const int which = blockIdx.y;
    const float4* in = (which == 0) ? a : (which == 1) ? b : (which == 2) ? c : d;
    uint2* out = (which == 0) ? oa : (which == 1) ? ob : (which == 2) ? oc : od;
    const int n4 = NE * NE / 4;
    int i = blockIdx.x * 256 + threadIdx.x;
    float4 v0 = in[i], v1 = in[i + n4/2];
    out[i]        = make_uint2(pack_h2(v0.x, v0.y), pack_h2(v0.z, v0.w));
    out[i + n4/2] = make_uint2(pack_h2(v1.x, v1.y), pack_h2(v1.z, v1.w));
}

// ---------------------------------------------------------------------------
// fp16 HMMA GEMM core: C = X @ W^T + bias (optionally *scale).
// MODE 0: fp32 out.  MODE 1: fp16 scatter [B,H,T,D].
// ---------------------------------------------------------------------------
#define PITCH_B 80
#define MAT_BYTES (128*PITCH_B)
#define STAGE_BYTES (2*MAT_BYTES)
#define NCHUNK (NE/32)

template<int MODE>
__device__ __forceinline__ void gemm_core(
    const __half* __restrict__ X, const __half* __restrict__ W,
    const float* __restrict__ bias, float* __restrict__ C,
    __half* __restrict__ Ch, float scale, char* smem)
{
    const uint32_t sb = smem_u32(smem);
    const int tid = threadIdx.x;
    const int wid = tid >> 5, lane = tid & 31;
    const int wm = wid >> 1, wn = wid & 1;
    const int n0 = blockIdx.x * 128, m0 = blockIdx.y * 128;

    const __half* bases[2] = { X, W };

    const int lr = lane & 15;
    const int kb8 = (lane >> 4) << 4;
    uint32_t aoff[2], boff[4];
    #pragma unroll
    for (int i = 0; i < 2; ++i)
        aoff[i] = (uint32_t)((wm*32 + i*16 + lr) * PITCH_B + kb8);
    #pragma unroll
    for (int j = 0; j < 4; ++j)
        boff[j] = (uint32_t)((wn*64 + j*16 + lr) * PITCH_B + kb8);

    float acc[2][8][4];
    #pragma unroll
    for (int i = 0; i < 2; ++i)
        #pragma unroll
        for (int j = 0; j < 8; ++j)
            #pragma unroll
            for (int r = 0; r < 4; ++r) acc[i][j][r] = 0.f;

    auto load_stage = [&](int stage, int kt) {
        const uint32_t sbase = sb + stage * STAGE_BYTES;
        #pragma unroll
        for (int t = 0; t < 2; ++t) {
            #pragma unroll
            for (int it = 0; it < 2; ++it) {
                int idx = tid + it * 256;
                int row = idx >> 2, c16 = idx & 3;
                int rg = ((t == 0) ? m0 : n0) + row;
                const __half* src = bases[t] + (long)rg * NE + kt + c16 * 8;
                uint32_t dst = sbase + t * MAT_BYTES + row * PITCH_B + c16 * 16;
                CP_ASYNC16(dst, src);
            }
        }
        CP_COMMIT();
    };

    load_stage(0, 0);

    for (int c = 0; c < NCHUNK; ++c) {
        if (c + 1 < NCHUNK) {
            load_stage((c + 1) & 1, (c + 1) * 32);
            CP_WAIT(1);
        } else {
            CP_WAIT(0);
        }
        __syncthreads();

        const uint32_t sA = sb + (c & 1) * STAGE_BYTES;
        const uint32_t sB = sA + MAT_BYTES;

        #pragma unroll
        for (int ks = 0; ks < 2; ++ks) {
            const uint32_t kbyte = ks * 32;
            uint32_t a[2][4], bmat[4][4];
            #pragma unroll
            for (int i = 0; i < 2; ++i)
                ldsm_x4(a[i][0], a[i][1], a[i][2], a[i][3], sA + aoff[i] + kbyte);
            #pragma unroll
            for (int j = 0; j < 4; ++j)
                ldsm_x4(bmat[j][0], bmat[j][1], bmat[j][2], bmat[j][3], sB + boff[j] + kbyte);
            #pragma unroll
            for (int i = 0; i < 2; ++i)
                #pragma unroll
                for (int j = 0; j < 4; ++j) {
                    mma_f16(acc[i][2*j],   a[i], bmat[j][0], bmat[j][2]);
                    mma_f16(acc[i][2*j+1], a[i], bmat[j][1], bmat[j][3]);
                }
        }
        __syncthreads();
    }

    const int qr = lane >> 2, qc = (lane & 3) * 2;
    #pragma unroll
    for (int i = 0; i < 2; ++i) {
        #pragma unroll
        for (int j = 0; j < 8; ++j) {
            const int n = n0 + wn*64 + j*8 + qc;
            const float b0 = bias[n], b1 = bias[n + 1];
            #pragma unroll
            for (int r8 = 0; r8 < 2; ++r8) {
                const int m = m0 + wm*32 + i*16 + qr + r8*8;
                float vx = acc[i][j][r8*2]     + b0;
                float vy = acc[i][j][r8*2 + 1] + b1;
                if (MODE == 0) {
                    *reinterpret_cast<float2*>(&C[(long)m * NE + n]) = make_float2(vx, vy);
                } else {
                    const int b = m >> 11, t = m & 2047, h = n >> 6, d = n & 63;
                    const long off = ((((long)(b*NH + h) * NT) + t) << 6) + d;
                    *reinterpret_cast<uint32_t*>(&Ch[off]) = pack_h2(vx * scale, vy * scale);
                }
            }
        }
    }
}

// log2(e) folded into Q so softmax can use raw ex2
#define QSCALE (0.125f * 1.44269504088896340736f)

// merged Q/K/V projection: grid.z selects which
__global__ __launch_bounds__(256) void gemm_qkv()
{
    extern __shared__ __align__(256) char smem[];
    const int z = blockIdx.z;
    const __half* X = (z == 0) ? g_xq : (z == 1) ? g_xk : g_xv;
    const __half* W = (z == 0) ? g_wq : (z == 1) ? g_wk : g_wv;
    // biases passed via __constant__-like globals is messy; use param-free:
    // we stash bias pointers in device globals set by memcpy? Simpler: biases
    // are kernel args in the launcher version below.
    // (this kernel body replaced by gemm_qkv_args)
}

__global__ __launch_bounds__(256) void gemm_qkv_args(
    const float* __restrict__ bq, const float* __restrict__ bk,
    const float* __restrict__ bv)
{
    extern __shared__ __align__(256) char smem[];
    const int z = blockIdx.z;
    const __half* X = (z == 0) ? g_xq : (z == 1) ? g_xk : g_xv;
    const __half* W = (z == 0) ? g_wq : (z == 1) ? g_wk : g_wv;
    const float* bias = (z == 0) ? bq : (z == 1) ? bk : bv;
    __half* Ch = (z == 0) ? g_qh : (z == 1) ? g_kh : g_vh;
    const float scale = (z == 0) ? QSCALE : 1.f;
    gemm_core<1>(X, W, bias, nullptr, Ch, scale, smem);
}

__global__ __launch_bounds__(256) void gemm_out(
    const float* __restrict__ bias, float* __restrict__ C)
{
    extern __shared__ __align__(256) char smem[];
    gemm_core<0>(g_xo, g_wo, bias, C, nullptr, 1.f, smem);
}

// ---------------------------------------------------------------------------
// fp16 tensor-core causal flash attention, base-2 softmax, LPT scheduling.
// grid = (64, 1, 16): blockIdx.x = b*16+h? (bh), blockIdx.z -> qt = 15-z (LPT).
// ---------------------------------------------------------------------------
#define APITCH 144
#define QBYTES (128*APITCH)
#define KVMAT  (64*APITCH)
#define KVSTAGE (2*KVMAT)
#define OFF_KV QBYTES
#define ATTN_SMEM (OFF_KV + 2*KVSTAGE)   // 55296

__global__ __launch_bounds__(256) void attn_f16()
{
    extern __shared__ __align__(256) char smem[];
    const uint32_t sb = smem_u32(smem);
    const int tid = threadIdx.x, wid = tid >> 5, lane = tid & 31;
    const int qt = 15 - blockIdx.z;          // LPT: longest first
    const int bh = blockIdx.x;
    const int h = bh & 15, b = bh >> 4;

    const long hb = (long)(b*NH + h) * NT * ND;
    const __half* Qg = g_qh + hb + (long)qt*128*ND;
    const __half* srcsKV[2] = { g_kh + hb, g_vh + hb };

    #pragma unroll
    for (int it = 0; it < 4; ++it) {
        int idx = tid + it * 256;
        int row = idx >> 3, c16 = idx & 7;
        CP_ASYNC16(sb + row*APITCH + c16*16, Qg + (long)row*ND + c16*8);
    }
    auto load_kv = [&](int stage, int kt) {
        const uint32_t sbase = sb + OFF_KV + stage * KVSTAGE;
        #pragma unroll
        for (int t = 0; t < 2; ++t) {
            #pragma unroll
            for (int it = 0; it < 2; ++it) {
                int idx = tid + it * 256;
                int row = idx >> 3, c16 = idx & 7;
                CP_ASYNC16(sbase + t*KVMAT + row*APITCH + c16*16,
                           srcsKV[t] + (long)(kt*64 + row)*ND + c16*8);
            }
        }
        CP_COMMIT();
    };
    load_kv(0, 0);

    const int lr = lane & 15;
    const int kb16 = (lane >> 4) << 4;
    const uint32_t aoffQ = (uint32_t)((wid*16 + lr) * APITCH + kb16);
    const uint32_t koff  = (uint32_t)(lr * APITCH + kb16);

    float m0 = -INFINITY, m1 = -INFINITY, l0 = 0.f, l1 = 0.f;
    float o[8][4];
    #pragma unroll
    for (int j = 0; j < 8; ++j)
        #pragma unroll
        for (int r = 0; r < 4; ++r) o[j][r] = 0.f;

    const int nkt = 2*qt + 2;
    const int rowg0 = qt*128 + wid*16 + (lane >> 2);
    const int qc2 = (lane & 3) * 2;

    for (int kt = 0; kt < nkt; ++kt) {
        if (kt + 1 < nkt) { load_kv((kt + 1) & 1, kt + 1); CP_WAIT(1); }
        else              { CP_WAIT(0); }
        __syncthreads();

        const uint32_t sK = sb + OFF_KV + (kt & 1) * KVSTAGE;
        const uint32_t sV = sK + KVMAT;

        // ---- S = Q @ K^T (S already in log2 domain via QSCALE) ----
        float s[8][4];
        #pragma unroll
        for (int j = 0; j < 8; ++j)
            #pragma unroll
            for (int r = 0; r < 4; ++r) s[j][r] = 0.f;

        #pragma unroll
        for (int ks = 0; ks < 4; ++ks) {
            const uint32_t kb = ks * 32;
            uint32_t a[4], bm[4][4];
            ldsm_x4(a[0], a[1], a[2], a[3], sb + aoffQ + kb);
            #pragma unroll
            for (int t = 0; t < 4; ++t)
                ldsm_x4(bm[t][0], bm[t][1], bm[t][2], bm[t][3], sK + koff + t*16*APITCH + kb);
            #pragma unroll
            for (int t = 0; t < 4; ++t) {
                mma_f16(s[2*t],   a, bm[t][0], bm[t][2]);
                mma_f16(s[2*t+1], a, bm[t][1], bm[t][3]);
            }
        }

        // ---- causal mask ----
        if (kt >= 2*qt) {
            const int colbase = kt*64 + qc2;
            #pragma unroll
            for (int j = 0; j < 8; ++j) {
                int c0 = colbase + j*8, c1 = c0 + 1;
                if (c0 > rowg0)     s[j][0] = -1e30f;
                if (c1 > rowg0)     s[j][1] = -1e30f;
                if (c0 > rowg0 + 8) s[j][2] = -1e30f;
                if (c1 > rowg0 + 8) s[j][3] = -1e30f;
            }
        }

        // ---- streaming softmax (base-2) ----
        float rm0 = -1e30f, rm1 = -1e30f;
        #pragma unroll
        for (int j = 0; j < 8; ++j) {
            rm0 = fmaxf(rm0, fmaxf(s[j][0], s[j][1]));
            rm1 = fmaxf(rm1, fmaxf(s[j][2], s[j][3]));
        }
        rm0 = fmaxf(rm0, __shfl_xor_sync(0xffffffffu, rm0, 1));
        rm0 = fmaxf(rm0, __shfl_xor_sync(0xffffffffu, rm0, 2));
        rm1 = fmaxf(rm1, __shfl_xor_sync(0xffffffffu, rm1, 1));
        rm1 = fmaxf(rm1, __shfl_xor_sync(0xffffffffu, rm1, 2));

        // renormalize only if any row max in this warp advanced
        const bool upd = (rm0 > m0) | (rm1 > m1);
        if (__ballot_sync(0xffffffffu, upd)) {
            const float mn0 = fmaxf(m0, rm0), mn1 = fmaxf(m1, rm1);
            const float cr0 = ex2(m0 - mn0), cr1 = ex2(m1 - mn1);
            l0 *= cr0; l1 *= cr1;
            #pragma unroll
            for (int j = 0; j < 8; ++j) {
                o[j][0] *= cr0; o[j][1] *= cr0;
                o[j][2] *= cr1; o[j][3] *= cr1;
            }
            m0 = mn0; m1 = mn1;
        }

        float sum0 = 0.f, sum1 = 0.f;
        #pragma unroll
        for (int j = 0; j < 8; ++j) {
            s[j][0] = ex2(s[j][0] - m0);
            s[j][1] = ex2(s[j][1] - m0);
            s[j][2] = ex2(s[j][2] - m1);
            s[j][3] = ex2(s[j][3] - m1);
            sum0 += s[j][0] + s[j][1];
            sum1 += s[j][2] + s[j][3];
        }
        sum0 += __shfl_xor_sync(0xffffffffu, sum0, 1);
        sum0 += __shfl_xor_sync(0xffffffffu, sum0, 2);
        sum1 += __shfl_xor_sync(0xffffffffu, sum1, 1);
        sum1 += __shfl_xor_sync(0xffffffffu, sum1, 2);
        l0 += sum0; l1 += sum1;

        // ---- O += P @ V ----
        #pragma unroll
        for (int ks = 0; ks < 4; ++ks) {
            uint32_t p[4];
            {
                const float* r0 = s[2*ks];
                const float* r1 = s[2*ks+1];
                p[0] = pack_h2(r0[0], r0[1]);
                p[1] = pack_h2(r0[2], r0[3]);
                p[2] = pack_h2(r1[0], r1[1]);
                p[3] = pack_h2(r1[2], r1[3]);
            }
            const uint32_t vrow = (uint32_t)((ks*16 + lr) * APITCH + kb16);
            uint32_t v[4][4];
            #pragma unroll
            for (int t = 0; t < 4; ++t)
                ldsm_x4_t(v[t][0], v[t][1], v[t][2], v[t][3], sV + vrow + t*32);
            #pragma unroll
            for (int t = 0; t < 4; ++t) {
                mma_f16(o[2*t],   p, v[t][0], v[t][1]);
                mma_f16(o[2*t+1], p, v[t][2], v[t][3]);
            }
        }
        __syncthreads();
    }

    // ---- finalize ----
    const float il0 = 1.f / l0, il1 = 1.f / l1;
    const int t0 = qt*128 + wid*16 + (lane >> 2);
    const long rowbase = ((long)b*NT + t0) * NE + h*64;
    #pragma unroll
    for (int j = 0; j < 8; ++j) {
        const int d = j*8 + qc2;
        *reinterpret_cast<uint32_t*>(&g_xo[rowbase + d]) =
            pack_h2(o[j][0]*il0, o[j][1]*il0);
        *reinterpret_cast<uint32_t*>(&g_xo[rowbase + 8*NE + d]) =
            pack_h2(o[j][2]*il1, o[j][3]*il1);
    }
}

// ---------------------------------------------------------------------------
extern "C" void kernel_launch(void* const* d_in, const int* in_sizes, int n_in,
                              void* d_out, int out_size)
{
    const float* query  = (const float*)d_in[0];
    const float* key_in = (const float*)d_in[1];
    const float* value  = (const float*)d_in[2];
    // d_in[3] = mask (exact tril -> causal predicate, not read)
    const float* Wq = (const float*)d_in[4];
    const float* bq = (const float*)d_in[5];
    const float* Wk = (const float*)d_in[6];
    const float* bk = (const float*)d_in[7];
    const float* Wv = (const float*)d_in[8];
    const float* bv = (const float*)d_in[9];
    const float* Wo = (const float*)d_in[10];
    const float* bo = (const float*)d_in[11];
    float* out = (float*)d_out;

    __half *xq, *xk, *xv, *wq, *wk, *wv, *wo;
    cudaGetSymbolAddress((void**)&xq, g_xq);
    cudaGetSymbolAddress((void**)&xk, g_xk);
    cudaGetSymbolAddress((void**)&xv, g_xv);
    cudaGetSymbolAddress((void**)&wq, g_wq);
    cudaGetSymbolAddress((void**)&wk, g_wk);
    cudaGetSymbolAddress((void**)&wv, g_wv);
    cudaGetSymbolAddress((void**)&wo, g_wo);

    const int gemm_smem = 2 * STAGE_BYTES;   // 40960
    cudaFuncSetAttribute(gemm_qkv_args, cudaFuncAttributeMaxDynamicSharedMemorySize, gemm_smem);
    cudaFuncSetAttribute(gemm_out, cudaFuncAttributeMaxDynamicSharedMemorySize, gemm_smem);
    cudaFuncSetAttribute(attn_f16, cudaFuncAttributeMaxDynamicSharedMemorySize, ATTN_SMEM);

    const int n4x = NM * NE / 4;   // 2097152
    const int n4w = NE * NE / 4;   // 262144

    // conversions (merged)
    conv_in3<<<dim3(n4x/512, 3), 256>>>((const float4*)query, (const float4*)key_in,
                                        (const float4*)value,
                                        (uint2*)xq, (uint2*)xk, (uint2*)xv);
    conv_w4<<<dim3(n4w/512, 4), 256>>>((const float4*)Wq, (const float4*)Wk,
                                       (const float4*)Wv, (const float4*)Wo,
                                       (uint2*)wq, (uint2*)wk, (uint2*)wv, (uint2*)wo);

    // merged Q/K/V projections
    gemm_qkv_args<<<dim3(NE/128, NM/128, 3), 256, gemm_smem>>>(bq, bk, bv);

    // attention (LPT: qt = 15 - blockIdx.z)
    attn_f16<<<dim3(NB*NH, 1, 16), 256, ATTN_SMEM>>>();

    // output projection
    gemm_out<<<dim3(NE/128, NM/128), 256, gemm_smem>>>(bo, out);
}